// round 1
// baseline (speedup 1.0000x reference)
#include <cuda_runtime.h>
#include <cuda_bf16.h>
#include <math.h>

// Problem constants
#define S_LEN 2048
#define HID   4096
#define NHEAD 32
#define HD    128
#define QKV_N 12288   // 3*HID
#define QKV_LD 12288

// Scratch (allocation-free rule: __device__ globals)
__device__ float g_qkv[(size_t)S_LEN * QKV_N];   // [2048][12288]
__device__ float g_ctx[(size_t)S_LEN * HID];     // [2048][4096]

// ---------------------------------------------------------------------------
// SGEMM: C[m,n] = sum_k A[m,k]*B[n,k] + bias[n]   (NT, both row-major, K inner)
// BM=BN=128, BK=8, 256 threads, 8x8 per-thread microtile.
// ---------------------------------------------------------------------------
#define BM 128
#define BN 128
#define BKK 8

__global__ __launch_bounds__(256)
void sgemm_nt_bias(const float* __restrict__ A, const float* __restrict__ B,
                   const float* __restrict__ bias, float* __restrict__ C,
                   int M, int N, int K)
{
    __shared__ float As[BKK][BM];
    __shared__ float Bs[BKK][BN];

    const int tid = threadIdx.x;
    const int bm = blockIdx.y * BM;
    const int bn = blockIdx.x * BN;

    const int l_row = tid >> 1;          // 0..127
    const int l_col = (tid & 1) * 4;     // 0 or 4

    const int ty = tid >> 4;             // 0..15
    const int tx = tid & 15;             // 0..15

    float acc[8][8];
    #pragma unroll
    for (int i = 0; i < 8; i++)
        #pragma unroll
        for (int j = 0; j < 8; j++) acc[i][j] = 0.f;

    const float* Aptr = A + (size_t)(bm + l_row) * K + l_col;
    const float* Bptr = B + (size_t)(bn + l_row) * K + l_col;

    for (int k0 = 0; k0 < K; k0 += BKK) {
        float4 a4 = *(const float4*)(Aptr + k0);
        float4 b4 = *(const float4*)(Bptr + k0);
        __syncthreads();
        As[l_col + 0][l_row] = a4.x;
        As[l_col + 1][l_row] = a4.y;
        As[l_col + 2][l_row] = a4.z;
        As[l_col + 3][l_row] = a4.w;
        Bs[l_col + 0][l_row] = b4.x;
        Bs[l_col + 1][l_row] = b4.y;
        Bs[l_col + 2][l_row] = b4.z;
        Bs[l_col + 3][l_row] = b4.w;
        __syncthreads();

        #pragma unroll
        for (int k = 0; k < BKK; k++) {
            float4 a0 = *(const float4*)&As[k][ty * 8];
            float4 a1 = *(const float4*)&As[k][ty * 8 + 4];
            float4 b0 = *(const float4*)&Bs[k][tx * 8];
            float4 b1 = *(const float4*)&Bs[k][tx * 8 + 4];
            float ar[8] = {a0.x, a0.y, a0.z, a0.w, a1.x, a1.y, a1.z, a1.w};
            float br[8] = {b0.x, b0.y, b0.z, b0.w, b1.x, b1.y, b1.z, b1.w};
            #pragma unroll
            for (int i = 0; i < 8; i++)
                #pragma unroll
                for (int j = 0; j < 8; j++)
                    acc[i][j] = fmaf(ar[i], br[j], acc[i][j]);
        }
    }

    #pragma unroll
    for (int i = 0; i < 8; i++) {
        float* crow = C + (size_t)(bm + ty * 8 + i) * N + bn + tx * 8;
        #pragma unroll
        for (int j = 0; j < 8; j++)
            crow[j] = acc[i][j] + bias[bn + tx * 8 + j];
    }
}

// ---------------------------------------------------------------------------
// RoPE (in-place on g_qkv). ROT=32, pairs (d, d+16), angle = s * 10000^(-2d/32)
// fp64 trig: angles up to ~2047 rad, keep abs error tiny.
// grid(2048, 32), 16 threads
// ---------------------------------------------------------------------------
__global__ void rope_kernel(float* __restrict__ qkv)
{
    int s = blockIdx.x;
    int h = blockIdx.y;
    int d = threadIdx.x;   // 0..15

    double inv = pow(10000.0, -(double)(2 * d) / 32.0);
    double ang = (double)s * inv;
    float c = (float)cos(ang);
    float sn = (float)sin(ang);

    float* base = qkv + (size_t)s * QKV_LD + h * 384;

    // q
    {
        float x1 = base[d];
        float x2 = base[d + 16];
        base[d]      = x1 * c - x2 * sn;
        base[d + 16] = x2 * c + x1 * sn;
    }
    // k
    {
        float x1 = base[128 + d];
        float x2 = base[128 + d + 16];
        base[128 + d]      = x1 * c - x2 * sn;
        base[128 + d + 16] = x2 * c + x1 * sn;
    }
}

// ---------------------------------------------------------------------------
// Flash attention, fp32. BQ=BKV=64, 256 threads (16x16), 4x4 S-microtile,
// online softmax, causal tile skipping. Q/K stored transposed in smem.
// grid(S/BQ=32, NHEAD=32)
// ---------------------------------------------------------------------------
#define BQ 64
#define BKVT 64
#define SQ 65     // padded stride for transposed Q/K tiles [HD][SQ]
#define PSS 68    // padded stride for P tile [BQ][PSS]

__global__ __launch_bounds__(256)
void flash_kernel(const float* __restrict__ qkv, float* __restrict__ ctx)
{
    extern __shared__ float sm[];
    float* Qst = sm;                    // [HD][SQ]
    float* Kst = Qst + HD * SQ;         // [HD][SQ]
    float* Vs  = Kst + HD * SQ;         // [BKVT][HD]
    float* Ps  = Vs + BKVT * HD;        // [BQ][PSS]

    const int qb = blockIdx.x;
    const int h  = blockIdx.y;
    const int tid = threadIdx.x;
    const int ty = tid >> 4;
    const int tx = tid & 15;
    const int q0 = qb * BQ;

    const float* qbase = qkv + (size_t)h * 384;
    const float* kbase = qbase + 128;
    const float* vbase = qbase + 256;

    // Load Q tile transposed: Qst[d][i] = Q[q0+i][d]
    for (int it = tid; it < BQ * (HD / 4); it += 256) {
        int i = it >> 5;            // row within tile (32 float4 per row)
        int c = (it & 31) * 4;      // dim
        float4 v4 = *(const float4*)(qbase + (size_t)(q0 + i) * QKV_LD + c);
        Qst[(c + 0) * SQ + i] = v4.x;
        Qst[(c + 1) * SQ + i] = v4.y;
        Qst[(c + 2) * SQ + i] = v4.z;
        Qst[(c + 3) * SQ + i] = v4.w;
    }

    float mi[4], li[4], O[4][8];
    #pragma unroll
    for (int i = 0; i < 4; i++) {
        mi[i] = -1e30f; li[i] = 0.f;
        #pragma unroll
        for (int j = 0; j < 8; j++) O[i][j] = 0.f;
    }

    const float scale = 0.08838834764831845f;   // 1/sqrt(128)

    for (int kb0 = 0; kb0 <= q0; kb0 += BKVT) {
        __syncthreads();   // previous iteration done reading Kst/Vs/Ps
        // Load K tile transposed + V tile row-major
        for (int it = tid; it < BKVT * (HD / 4); it += 256) {
            int j = it >> 5;
            int c = (it & 31) * 4;
            float4 k4 = *(const float4*)(kbase + (size_t)(kb0 + j) * QKV_LD + c);
            Kst[(c + 0) * SQ + j] = k4.x;
            Kst[(c + 1) * SQ + j] = k4.y;
            Kst[(c + 2) * SQ + j] = k4.z;
            Kst[(c + 3) * SQ + j] = k4.w;
            float4 v4 = *(const float4*)(vbase + (size_t)(kb0 + j) * QKV_LD + c);
            *(float4*)&Vs[j * HD + c] = v4;
        }
        __syncthreads();

        // S tile: s[i][j] = sum_d Qst[d][ty*4+i] * Kst[d][tx*4+j]
        float s[4][4];
        #pragma unroll
        for (int i = 0; i < 4; i++)
            #pragma unroll
            for (int j = 0; j < 4; j++) s[i][j] = 0.f;

        for (int d = 0; d < HD; d++) {
            float ar[4], br[4];
            #pragma unroll
            for (int i = 0; i < 4; i++) ar[i] = Qst[d * SQ + ty * 4 + i];
            #pragma unroll
            for (int j = 0; j < 4; j++) br[j] = Kst[d * SQ + tx * 4 + j];
            #pragma unroll
            for (int i = 0; i < 4; i++)
                #pragma unroll
                for (int j = 0; j < 4; j++)
                    s[i][j] = fmaf(ar[i], br[j], s[i][j]);
        }

        const bool diag = (kb0 == q0);

        // scale + causal mask + online softmax
        #pragma unroll
        for (int i = 0; i < 4; i++) {
            int qrow = q0 + ty * 4 + i;
            #pragma unroll
            for (int j = 0; j < 4; j++) {
                float v = s[i][j] * scale;
                if (diag) {
                    int krow = kb0 + tx * 4 + j;
                    if (krow > qrow) v = -1e30f;
                }
                s[i][j] = v;
            }
            float m = fmaxf(fmaxf(s[i][0], s[i][1]), fmaxf(s[i][2], s[i][3]));
            #pragma unroll
            for (int off = 1; off < 16; off <<= 1)
                m = fmaxf(m, __shfl_xor_sync(0xffffffffu, m, off));
            float mnew = fmaxf(mi[i], m);
            float corr = expf(mi[i] - mnew);
            mi[i] = mnew;
            float rs = 0.f;
            #pragma unroll
            for (int j = 0; j < 4; j++) {
                float p = expf(s[i][j] - mnew);
                s[i][j] = p;
                rs += p;
            }
            #pragma unroll
            for (int off = 1; off < 16; off <<= 1)
                rs += __shfl_xor_sync(0xffffffffu, rs, off);
            li[i] = li[i] * corr + rs;
            #pragma unroll
            for (int j = 0; j < 8; j++) O[i][j] *= corr;
            #pragma unroll
            for (int j = 0; j < 4; j++)
                Ps[(ty * 4 + i) * PSS + tx * 4 + j] = s[i][j];
        }
        __syncthreads();

        // O += P @ V : thread owns rows ty*4..+3, cols tx*8..+7
        for (int j = 0; j < BKVT; j++) {
            float pv[4];
            #pragma unroll
            for (int i = 0; i < 4; i++) pv[i] = Ps[(ty * 4 + i) * PSS + j];
            float4 v0 = *(const float4*)&Vs[j * HD + tx * 8];
            float4 v1 = *(const float4*)&Vs[j * HD + tx * 8 + 4];
            #pragma unroll
            for (int i = 0; i < 4; i++) {
                O[i][0] = fmaf(pv[i], v0.x, O[i][0]);
                O[i][1] = fmaf(pv[i], v0.y, O[i][1]);
                O[i][2] = fmaf(pv[i], v0.z, O[i][2]);
                O[i][3] = fmaf(pv[i], v0.w, O[i][3]);
                O[i][4] = fmaf(pv[i], v1.x, O[i][4]);
                O[i][5] = fmaf(pv[i], v1.y, O[i][5]);
                O[i][6] = fmaf(pv[i], v1.z, O[i][6]);
                O[i][7] = fmaf(pv[i], v1.w, O[i][7]);
            }
        }
    }

    // Epilogue: ctx[s][h*128 + c] = O / l
    #pragma unroll
    for (int i = 0; i < 4; i++) {
        float inv = 1.f / li[i];
        int srow = q0 + ty * 4 + i;
        float* dst = ctx + (size_t)srow * HID + h * HD + tx * 8;
        #pragma unroll
        for (int j = 0; j < 8; j++) dst[j] = O[i][j] * inv;
    }
}

// ---------------------------------------------------------------------------
// Launch
// ---------------------------------------------------------------------------
extern "C" void kernel_launch(void* const* d_in, const int* in_sizes, int n_in,
                              void* d_out, int out_size)
{
    const float* hs    = (const float*)d_in[0];
    // d_in[1] = attention_mask (causal, known statically) — unused
    const float* Wqkv  = (const float*)d_in[2];
    const float* bqkv  = (const float*)d_in[3];
    const float* Wd    = (const float*)d_in[4];
    const float* bd    = (const float*)d_in[5];
    float* out = (float*)d_out;

    float* qkv = nullptr;
    float* ctx = nullptr;
    cudaGetSymbolAddress((void**)&qkv, g_qkv);
    cudaGetSymbolAddress((void**)&ctx, g_ctx);

    // 1) QKV GEMM: [2048,4096] x [12288,4096]^T -> [2048,12288]
    {
        dim3 grid(QKV_N / BN, S_LEN / BM);
        sgemm_nt_bias<<<grid, 256>>>(hs, Wqkv, bqkv, qkv, S_LEN, QKV_N, HID);
    }

    // 2) RoPE in place on q,k (first 32 dims each)
    {
        dim3 grid(S_LEN, NHEAD);
        rope_kernel<<<grid, 16>>>(qkv);
    }

    // 3) Flash attention -> ctx [2048,4096]
    {
        int smem_bytes = (HD * SQ + HD * SQ + BKVT * HD + BQ * PSS) * (int)sizeof(float);
        cudaFuncSetAttribute(flash_kernel,
                             cudaFuncAttributeMaxDynamicSharedMemorySize, smem_bytes);
        dim3 grid(S_LEN / BQ, NHEAD);
        flash_kernel<<<grid, 256, smem_bytes>>>(qkv, ctx);
    }

    // 4) Dense GEMM: [2048,4096] x [4096,4096]^T -> out
    {
        dim3 grid(HID / BN, S_LEN / BM);
        sgemm_nt_bias<<<grid, 256>>>(ctx, Wd, bd, out, S_LEN, HID, HID);
    }
}

// round 5
// speedup vs baseline: 1.8355x; 1.8355x over previous
#include <cuda_runtime.h>
#include <cuda_bf16.h>
#include <math.h>
#include <cstdint>

// Problem constants
#define S_LEN 2048
#define HID   4096
#define NHEAD 32
#define HD    128
#define QKV_N 12288   // 3*HID
#define QKV_LD 12288

// ---------------------------------------------------------------------------
// Scratch (__device__ globals; allocation-free rule)
// ---------------------------------------------------------------------------
__device__ float g_qkv[(size_t)S_LEN * QKV_N];   // [2048][12288] fp32
__device__ float g_ctx[(size_t)S_LEN * HID];     // [2048][4096] fp32

__device__ __nv_bfloat16 g_hs_hi[(size_t)S_LEN * HID];
__device__ __nv_bfloat16 g_hs_lo[(size_t)S_LEN * HID];
__device__ __nv_bfloat16 g_wq_hi[(size_t)QKV_N * HID];
__device__ __nv_bfloat16 g_wq_lo[(size_t)QKV_N * HID];
__device__ __nv_bfloat16 g_wd_hi[(size_t)HID * HID];
__device__ __nv_bfloat16 g_wd_lo[(size_t)HID * HID];
__device__ __nv_bfloat16 g_ctx_hi[(size_t)S_LEN * HID];
__device__ __nv_bfloat16 g_ctx_lo[(size_t)S_LEN * HID];

// ---------------------------------------------------------------------------
// PTX helpers (portable subset only: cp.async / ldmatrix / mma.sync)
// ---------------------------------------------------------------------------
__device__ __forceinline__ uint32_t smem_u32(const void* p) {
    uint32_t a;
    asm("{ .reg .u64 t; cvta.to.shared.u64 t, %1; cvt.u32.u64 %0, t; }" : "=r"(a) : "l"(p));
    return a;
}

__device__ __forceinline__ void cp16(uint32_t dst, const void* src) {
    asm volatile("cp.async.cg.shared.global [%0], [%1], 16;" :: "r"(dst), "l"(src) : "memory");
}
#define CP_COMMIT() asm volatile("cp.async.commit_group;" ::: "memory")
#define CP_WAIT(n)  asm volatile("cp.async.wait_group %0;" :: "n"(n) : "memory")

#define LDSM4(r, addr) \
    asm volatile("ldmatrix.sync.aligned.m8n8.x4.shared.b16 {%0,%1,%2,%3}, [%4];" \
                 : "=r"((r)[0]), "=r"((r)[1]), "=r"((r)[2]), "=r"((r)[3]) : "r"(addr))

#define MMA16816(d, a, b0, b1) \
    asm volatile("mma.sync.aligned.m16n8k16.row.col.f32.bf16.bf16.f32 " \
                 "{%0,%1,%2,%3}, {%4,%5,%6,%7}, {%8,%9}, {%0,%1,%2,%3};" \
                 : "+f"((d)[0]), "+f"((d)[1]), "+f"((d)[2]), "+f"((d)[3]) \
                 : "r"((a)[0]), "r"((a)[1]), "r"((a)[2]), "r"((a)[3]), "r"(b0), "r"(b1))

// ---------------------------------------------------------------------------
// fp32 -> bf16 hi/lo split
// ---------------------------------------------------------------------------
__global__ __launch_bounds__(256)
void cvt_split(const float* __restrict__ x, __nv_bfloat16* __restrict__ hi,
               __nv_bfloat16* __restrict__ lo, size_t n)
{
    size_t i = ((size_t)blockIdx.x * blockDim.x + threadIdx.x) * 4;
    if (i >= n) return;
    float4 v = *(const float4*)(x + i);
    __nv_bfloat16 h0 = __float2bfloat16(v.x);
    __nv_bfloat16 h1 = __float2bfloat16(v.y);
    __nv_bfloat16 h2 = __float2bfloat16(v.z);
    __nv_bfloat16 h3 = __float2bfloat16(v.w);
    __nv_bfloat16 l0 = __float2bfloat16(v.x - __bfloat162float(h0));
    __nv_bfloat16 l1 = __float2bfloat16(v.y - __bfloat162float(h1));
    __nv_bfloat16 l2 = __float2bfloat16(v.z - __bfloat162float(h2));
    __nv_bfloat16 l3 = __float2bfloat16(v.w - __bfloat162float(h3));
    __nv_bfloat162 hp0{h0, h1}, hp1{h2, h3}, lp0{l0, l1}, lp1{l2, l3};
    *(uint2*)(hi + i) = make_uint2(*(uint32_t*)&hp0, *(uint32_t*)&hp1);
    *(uint2*)(lo + i) = make_uint2(*(uint32_t*)&lp0, *(uint32_t*)&lp1);
}

// ---------------------------------------------------------------------------
// mma.sync bf16x3 GEMM-NT: C[M,N] = A[M,K]*B[N,K]^T + bias
// BM=BN=128, BK=32, 256 threads (8 warps 4x2, warp tile 32x64).
// smem: per stage {Ahi,Alo,Bhi,Blo}, each [128][40] bf16 (pad stride 40).
// ---------------------------------------------------------------------------
#define BM 128
#define BN 128
#define BK 32
#define AST 40                        // padded stride (bf16 elems)
#define TERM_ELEM (128 * AST)         // 5120 elems
#define STAGE_ELEM (4 * TERM_ELEM)    // 20480 elems
#define GEMM_SMEM_BYTES (2 * STAGE_ELEM * 2)  // 81920 B

__global__ __launch_bounds__(256, 1)
void gemm_mma_bf16x3(const __nv_bfloat16* __restrict__ Ahi, const __nv_bfloat16* __restrict__ Alo,
                     const __nv_bfloat16* __restrict__ Bhi, const __nv_bfloat16* __restrict__ Blo,
                     const float* __restrict__ bias, float* __restrict__ C, int N, int K)
{
    extern __shared__ __align__(128) __nv_bfloat16 smem[];
    const uint32_t sb = smem_u32(smem);

    const int tid = threadIdx.x;
    const int wid = tid >> 5;
    const int lane = tid & 31;
    const int bm = blockIdx.y * BM;
    const int bn = blockIdx.x * BN;

    const int wm = (wid & 3) * 32;     // warp m offset
    const int wn = (wid >> 2) * 64;    // warp n offset

    // ldmatrix lane address components
    const int a_lr = lane & 15;               // row within 16
    const int a_kc = (lane >> 4) * 8;         // k-half
    const int b_nr = (lane & 7) | ((lane >> 4) << 3);  // n row within 16
    const int b_kc = ((lane >> 3) & 1) * 8;   // k-half

    const int NC = K / BK;

    // ---- stage loader: 512 16B-chunks per matrix, 2 per thread per matrix
    auto load_stage = [&](int s, int k0) {
        const uint32_t stage_b = sb + (uint32_t)s * STAGE_ELEM * 2;
        #pragma unroll
        for (int i = 0; i < 2; i++) {
            int t = tid + i * 256;
            int row = t >> 2;
            int c4 = t & 3;
            uint32_t doff = (uint32_t)(row * AST + c4 * 8) * 2;
            size_t aoff = (size_t)(bm + row) * K + k0 + c4 * 8;
            size_t boff = (size_t)(bn + row) * K + k0 + c4 * 8;
            cp16(stage_b + 0 * TERM_ELEM * 2 + doff, Ahi + aoff);
            cp16(stage_b + 1 * TERM_ELEM * 2 + doff, Alo + aoff);
            cp16(stage_b + 2 * TERM_ELEM * 2 + doff, Bhi + boff);
            cp16(stage_b + 3 * TERM_ELEM * 2 + doff, Blo + boff);
        }
    };

    float acc[2][8][4];
    #pragma unroll
    for (int mt = 0; mt < 2; mt++)
        #pragma unroll
        for (int nt = 0; nt < 8; nt++)
            #pragma unroll
            for (int r = 0; r < 4; r++) acc[mt][nt][r] = 0.f;

    load_stage(0, 0);
    CP_COMMIT();

    for (int c = 0; c < NC; ++c) {
        if (c + 1 < NC) {
            load_stage((c + 1) & 1, (c + 1) * BK);
            CP_COMMIT();
            CP_WAIT(1);
        } else {
            CP_WAIT(0);
        }
        __syncthreads();

        const uint32_t stage_b = sb + (uint32_t)(c & 1) * STAGE_ELEM * 2;
        const uint32_t sAhi = stage_b;
        const uint32_t sAlo = stage_b + TERM_ELEM * 2;
        const uint32_t sBhi = stage_b + 2 * TERM_ELEM * 2;
        const uint32_t sBlo = stage_b + 3 * TERM_ELEM * 2;

        #pragma unroll
        for (int ks = 0; ks < 2; ks++) {
            const int kof = ks * 16;
            uint32_t ahf[2][4], alf[2][4];
            #pragma unroll
            for (int mt = 0; mt < 2; mt++) {
                uint32_t ro = (uint32_t)((wm + mt * 16 + a_lr) * AST + kof + a_kc) * 2;
                LDSM4(ahf[mt], sAhi + ro);
                LDSM4(alf[mt], sAlo + ro);
            }
            uint32_t bhf[4][4], blf[4][4];
            #pragma unroll
            for (int bt = 0; bt < 4; bt++) {
                uint32_t ro = (uint32_t)((wn + bt * 16 + b_nr) * AST + kof + b_kc) * 2;
                LDSM4(bhf[bt], sBhi + ro);
                LDSM4(blf[bt], sBlo + ro);
            }
            #pragma unroll
            for (int mt = 0; mt < 2; mt++) {
                #pragma unroll
                for (int nt = 0; nt < 8; nt++) {
                    const uint32_t* bh = &bhf[nt >> 1][(nt & 1) * 2];
                    const uint32_t* bl = &blf[nt >> 1][(nt & 1) * 2];
                    MMA16816(acc[mt][nt], ahf[mt], bh[0], bh[1]);   // hi*hi
                    MMA16816(acc[mt][nt], alf[mt], bh[0], bh[1]);   // lo*hi
                    MMA16816(acc[mt][nt], ahf[mt], bl[0], bl[1]);   // hi*lo
                }
            }
        }
        __syncthreads();
    }

    // ---- epilogue: c-frag (m16n8): rows t/4, t/4+8; cols (t%4)*2, +1
    const int er = lane >> 2;
    const int ec = (lane & 3) * 2;
    #pragma unroll
    for (int mt = 0; mt < 2; mt++) {
        #pragma unroll
        for (int nt = 0; nt < 8; nt++) {
            int col = bn + wn + nt * 8 + ec;
            float b0 = bias[col], b1 = bias[col + 1];
            int row0 = bm + wm + mt * 16 + er;
            float2 v0 = make_float2(acc[mt][nt][0] + b0, acc[mt][nt][1] + b1);
            float2 v1 = make_float2(acc[mt][nt][2] + b0, acc[mt][nt][3] + b1);
            *(float2*)(C + (size_t)row0 * N + col) = v0;
            *(float2*)(C + (size_t)(row0 + 8) * N + col) = v1;
        }
    }
}

// ---------------------------------------------------------------------------
// RoPE (unchanged)
// ---------------------------------------------------------------------------
__global__ void rope_kernel(float* __restrict__ qkv)
{
    int s = blockIdx.x;
    int h = blockIdx.y;
    int d = threadIdx.x;   // 0..15

    double inv = pow(10000.0, -(double)(2 * d) / 32.0);
    double ang = (double)s * inv;
    float c = (float)cos(ang);
    float sn = (float)sin(ang);

    float* base = qkv + (size_t)s * QKV_LD + h * 384;
    {
        float x1 = base[d], x2 = base[d + 16];
        base[d] = x1 * c - x2 * sn;
        base[d + 16] = x2 * c + x1 * sn;
    }
    {
        float x1 = base[128 + d], x2 = base[128 + d + 16];
        base[128 + d] = x1 * c - x2 * sn;
        base[128 + d + 16] = x2 * c + x1 * sn;
    }
}

// ---------------------------------------------------------------------------
// Flash attention fp32 (unchanged from passing R1)
// ---------------------------------------------------------------------------
#define BQ 64
#define BKVT 64
#define SQ 65
#define PSS 68

__global__ __launch_bounds__(256)
void flash_kernel(const float* __restrict__ qkv, float* __restrict__ ctx)
{
    extern __shared__ float sm[];
    float* Qst = sm;
    float* Kst = Qst + HD * SQ;
    float* Vs  = Kst + HD * SQ;
    float* Ps  = Vs + BKVT * HD;

    const int qb = blockIdx.x;
    const int h  = blockIdx.y;
    const int tid = threadIdx.x;
    const int ty = tid >> 4;
    const int tx = tid & 15;
    const int q0 = qb * BQ;

    const float* qbase = qkv + (size_t)h * 384;
    const float* kbase = qbase + 128;
    const float* vbase = qbase + 256;

    for (int it = tid; it < BQ * (HD / 4); it += 256) {
        int i = it >> 5;
        int c = (it & 31) * 4;
        float4 v4 = *(const float4*)(qbase + (size_t)(q0 + i) * QKV_LD + c);
        Qst[(c + 0) * SQ + i] = v4.x;
        Qst[(c + 1) * SQ + i] = v4.y;
        Qst[(c + 2) * SQ + i] = v4.z;
        Qst[(c + 3) * SQ + i] = v4.w;
    }

    float mi[4], li[4], O[4][8];
    #pragma unroll
    for (int i = 0; i < 4; i++) {
        mi[i] = -1e30f; li[i] = 0.f;
        #pragma unroll
        for (int j = 0; j < 8; j++) O[i][j] = 0.f;
    }

    const float scale = 0.08838834764831845f;

    for (int kb0 = 0; kb0 <= q0; kb0 += BKVT) {
        __syncthreads();
        for (int it = tid; it < BKVT * (HD / 4); it += 256) {
            int j = it >> 5;
            int c = (it & 31) * 4;
            float4 k4 = *(const float4*)(kbase + (size_t)(kb0 + j) * QKV_LD + c);
            Kst[(c + 0) * SQ + j] = k4.x;
            Kst[(c + 1) * SQ + j] = k4.y;
            Kst[(c + 2) * SQ + j] = k4.z;
            Kst[(c + 3) * SQ + j] = k4.w;
            float4 v4 = *(const float4*)(vbase + (size_t)(kb0 + j) * QKV_LD + c);
            *(float4*)&Vs[j * HD + c] = v4;
        }
        __syncthreads();

        float s[4][4];
        #pragma unroll
        for (int i = 0; i < 4; i++)
            #pragma unroll
            for (int j = 0; j < 4; j++) s[i][j] = 0.f;

        for (int d = 0; d < HD; d++) {
            float ar[4], br[4];
            #pragma unroll
            for (int i = 0; i < 4; i++) ar[i] = Qst[d * SQ + ty * 4 + i];
            #pragma unroll
            for (int j = 0; j < 4; j++) br[j] = Kst[d * SQ + tx * 4 + j];
            #pragma unroll
            for (int i = 0; i < 4; i++)
                #pragma unroll
                for (int j = 0; j < 4; j++)
                    s[i][j] = fmaf(ar[i], br[j], s[i][j]);
        }

        const bool diag = (kb0 == q0);

        #pragma unroll
        for (int i = 0; i < 4; i++) {
            int qrow = q0 + ty * 4 + i;
            #pragma unroll
            for (int j = 0; j < 4; j++) {
                float v = s[i][j] * scale;
                if (diag) {
                    int krow = kb0 + tx * 4 + j;
                    if (krow > qrow) v = -1e30f;
                }
                s[i][j] = v;
            }
            float m = fmaxf(fmaxf(s[i][0], s[i][1]), fmaxf(s[i][2], s[i][3]));
            #pragma unroll
            for (int off = 1; off < 16; off <<= 1)
                m = fmaxf(m, __shfl_xor_sync(0xffffffffu, m, off));
            float mnew = fmaxf(mi[i], m);
            float corr = expf(mi[i] - mnew);
            mi[i] = mnew;
            float rs = 0.f;
            #pragma unroll
            for (int j = 0; j < 4; j++) {
                float p = expf(s[i][j] - mnew);
                s[i][j] = p;
                rs += p;
            }
            #pragma unroll
            for (int off = 1; off < 16; off <<= 1)
                rs += __shfl_xor_sync(0xffffffffu, rs, off);
            li[i] = li[i] * corr + rs;
            #pragma unroll
            for (int j = 0; j < 8; j++) O[i][j] *= corr;
            #pragma unroll
            for (int j = 0; j < 4; j++)
                Ps[(ty * 4 + i) * PSS + tx * 4 + j] = s[i][j];
        }
        __syncthreads();

        for (int j = 0; j < BKVT; j++) {
            float pv[4];
            #pragma unroll
            for (int i = 0; i < 4; i++) pv[i] = Ps[(ty * 4 + i) * PSS + j];
            float4 v0 = *(const float4*)&Vs[j * HD + tx * 8];
            float4 v1 = *(const float4*)&Vs[j * HD + tx * 8 + 4];
            #pragma unroll
            for (int i = 0; i < 4; i++) {
                O[i][0] = fmaf(pv[i], v0.x, O[i][0]);
                O[i][1] = fmaf(pv[i], v0.y, O[i][1]);
                O[i][2] = fmaf(pv[i], v0.z, O[i][2]);
                O[i][3] = fmaf(pv[i], v0.w, O[i][3]);
                O[i][4] = fmaf(pv[i], v1.x, O[i][4]);
                O[i][5] = fmaf(pv[i], v1.y, O[i][5]);
                O[i][6] = fmaf(pv[i], v1.z, O[i][6]);
                O[i][7] = fmaf(pv[i], v1.w, O[i][7]);
            }
        }
    }

    #pragma unroll
    for (int i = 0; i < 4; i++) {
        float inv = 1.f / li[i];
        int srow = q0 + ty * 4 + i;
        float* dst = ctx + (size_t)srow * HID + h * HD + tx * 8;
        #pragma unroll
        for (int j = 0; j < 8; j++) dst[j] = O[i][j] * inv;
    }
}

// ---------------------------------------------------------------------------
// Launch
// ---------------------------------------------------------------------------
extern "C" void kernel_launch(void* const* d_in, const int* in_sizes, int n_in,
                              void* d_out, int out_size)
{
    const float* hs   = (const float*)d_in[0];
    const float* Wqkv = (const float*)d_in[2];
    const float* bqkv = (const float*)d_in[3];
    const float* Wd   = (const float*)d_in[4];
    const float* bd   = (const float*)d_in[5];
    float* out = (float*)d_out;

    float *qkv, *ctx;
    __nv_bfloat16 *hs_hi, *hs_lo, *wq_hi, *wq_lo, *wd_hi, *wd_lo, *ctx_hi, *ctx_lo;
    cudaGetSymbolAddress((void**)&qkv, g_qkv);
    cudaGetSymbolAddress((void**)&ctx, g_ctx);
    cudaGetSymbolAddress((void**)&hs_hi, g_hs_hi);
    cudaGetSymbolAddress((void**)&hs_lo, g_hs_lo);
    cudaGetSymbolAddress((void**)&wq_hi, g_wq_hi);
    cudaGetSymbolAddress((void**)&wq_lo, g_wq_lo);
    cudaGetSymbolAddress((void**)&wd_hi, g_wd_hi);
    cudaGetSymbolAddress((void**)&wd_lo, g_wd_lo);
    cudaGetSymbolAddress((void**)&ctx_hi, g_ctx_hi);
    cudaGetSymbolAddress((void**)&ctx_lo, g_ctx_lo);

    cudaFuncSetAttribute(gemm_mma_bf16x3, cudaFuncAttributeMaxDynamicSharedMemorySize,
                         GEMM_SMEM_BYTES);

    // 0) split inputs into bf16 hi/lo
    {
        size_t n1 = (size_t)S_LEN * HID;
        size_t n2 = (size_t)QKV_N * HID;
        size_t n3 = (size_t)HID * HID;
        cvt_split<<<(unsigned)((n1 / 4 + 255) / 256), 256>>>(hs, hs_hi, hs_lo, n1);
        cvt_split<<<(unsigned)((n2 / 4 + 255) / 256), 256>>>(Wqkv, wq_hi, wq_lo, n2);
        cvt_split<<<(unsigned)((n3 / 4 + 255) / 256), 256>>>(Wd, wd_hi, wd_lo, n3);
    }

    // 1) QKV GEMM (mma.sync bf16x3): [2048,4096] x [12288,4096]^T -> g_qkv
    {
        dim3 grid(QKV_N / BN, S_LEN / BM);
        gemm_mma_bf16x3<<<grid, 256, GEMM_SMEM_BYTES>>>(hs_hi, hs_lo, wq_hi, wq_lo,
                                                        bqkv, qkv, QKV_N, HID);
    }

    // 2) RoPE
    {
        dim3 grid(S_LEN, NHEAD);
        rope_kernel<<<grid, 16>>>(qkv);
    }

    // 3) Flash attention -> ctx
    {
        int smem_bytes = (HD * SQ + HD * SQ + BKVT * HD + BQ * PSS) * (int)sizeof(float);
        cudaFuncSetAttribute(flash_kernel, cudaFuncAttributeMaxDynamicSharedMemorySize, smem_bytes);
        dim3 grid(S_LEN / BQ, NHEAD);
        flash_kernel<<<grid, 256, smem_bytes>>>(qkv, ctx);
    }

    // 3b) split ctx into bf16 hi/lo
    {
        size_t n1 = (size_t)S_LEN * HID;
        cvt_split<<<(unsigned)((n1 / 4 + 255) / 256), 256>>>(ctx, ctx_hi, ctx_lo, n1);
    }

    // 4) Dense GEMM (mma.sync bf16x3): [2048,4096] x [4096,4096]^T -> out
    {
        dim3 grid(HID / BN, S_LEN / BM);
        gemm_mma_bf16x3<<<grid, 256, GEMM_SMEM_BYTES>>>(ctx_hi, ctx_lo, wd_hi, wd_lo,
                                                        bd, out, HID, HID);
    }
}